// round 13
// baseline (speedup 1.0000x reference)
#include <cuda_runtime.h>
#include <cuda_bf16.h>
#include <math.h>

// Fixed problem shape
#define HH 128
#define GG 64
#define NN_MAX 100000
#define EE_MAX 1600000

typedef unsigned long long u64;
typedef unsigned int u32;

// Scratch: __device__ globals, referenced ONLY inside device code.
__device__ __nv_bfloat16 g_hb[NN_MAX * HH];     // node features (bf16)
__device__ __nv_bfloat16 g_aggrb[NN_MAX * HH];  // aggregate output (bf16)
__device__ float g_pool[GG * HH];
__device__ float g_cnt[GG];
__device__ float g_st[GG * 64];
__device__ int   g_idx64;           // 1 if edge_index/batch are int64

// Pre-converted bf16 weights, TRANSPOSED [c][k]: mats 0=W1L0,1=W2L0,2=W1L1,3=W2L1
__device__ __nv_bfloat16 g_Wt[4 * HH * HH];

// CSR scratch (built once per call; graph shared by both layers)
__device__ int   g_deg[NN_MAX];
__device__ int   g_rowptr[NN_MAX + 1];
__device__ int   g_cursor[NN_MAX];
__device__ int   g_bsum[512];
__device__ int   g_boff[512];
__device__ int   g_esrc[EE_MAX];
__device__ float g_eea[EE_MAX];

__device__ __forceinline__ void red_add_v2(float* p, float a, float b) {
    asm volatile("red.global.add.v2.f32 [%0], {%1,%2};"
                 :: "l"(p), "f"(a), "f"(b) : "memory");
}

// bf16 mma m16n8k16 (row.col): A 4 regs (8 bf16), B 2 regs (4 bf16), D 4 f32
__device__ __forceinline__ void mma_bf16(float d[4], const u32 a[4],
                                         const u32 b[2]) {
    asm("mma.sync.aligned.m16n8k16.row.col.f32.bf16.bf16.f32 "
        "{%0,%1,%2,%3}, {%4,%5,%6,%7}, {%8,%9}, {%0,%1,%2,%3};"
        : "+f"(d[0]), "+f"(d[1]), "+f"(d[2]), "+f"(d[3])
        : "r"(a[0]), "r"(a[1]), "r"(a[2]), "r"(a[3]), "r"(b[0]), "r"(b[1]));
}

__device__ __forceinline__ uint2 pack_bf16x4(float4 v) {
    __nv_bfloat162 p0 = __floats2bfloat162_rn(v.x, v.y);
    __nv_bfloat162 p1 = __floats2bfloat162_rn(v.z, v.w);
    uint2 o;
    o.x = *reinterpret_cast<u32*>(&p0);
    o.y = *reinterpret_cast<u32*>(&p1);
    return o;
}

__device__ __forceinline__ float4 ldhb4(const __nv_bfloat16* p) {
    uint2 rv = *(const uint2*)p;
    __nv_bfloat162 b0 = *reinterpret_cast<__nv_bfloat162*>(&rv.x);
    __nv_bfloat162 b1 = *reinterpret_cast<__nv_bfloat162*>(&rv.y);
    float2 f0 = __bfloat1622float2(b0);
    float2 f1 = __bfloat1622float2(b1);
    return make_float4(f0.x, f0.y, f1.x, f1.y);
}

// ---------------------------------------------------------------------------
__global__ void detect_kernel(const void* ei_raw, int n) {
    if (threadIdx.x == 0 && blockIdx.x == 0) {
        const long long* p = (const long long*)ei_raw;
        int ok = 1;
        for (int i = 0; i < 16; i++) {
            long long v = p[i];
            if (v < 0 || v >= (long long)n) ok = 0;
        }
        g_idx64 = ok;
    }
}

__global__ void zero_misc_kernel(int n) {
    int i = blockIdx.x * blockDim.x + threadIdx.x;
    if (i < n) g_deg[i] = 0;
    if (i < GG * HH) g_pool[i] = 0.0f;
    if (i < GG) g_cnt[i] = 0.0f;
}

// Pre-convert W1/W2 (both layers) to bf16, transposed [c][k].
__global__ void presplit_kernel(const float* __restrict__ w1,
                                const float* __restrict__ w2) {
    int i = blockIdx.x * blockDim.x + threadIdx.x;   // 0 .. 2*HH*HH-1
    if (i >= 2 * HH * HH) return;
    int l = i >> 14;
    int off = i & 16383;
    int k = off >> 7;
    int c = off & 127;
    g_Wt[(l * 2 + 0) * 16384 + c * HH + k] = __float2bfloat16(__ldg(w1 + i));
    g_Wt[(l * 2 + 1) * 16384 + c * HH + k] = __float2bfloat16(__ldg(w2 + i));
}

// ============================ CSR build (once) =============================
__global__ void csr_count_kernel(const void* __restrict__ ei_raw, int E, int n) {
    int e = blockIdx.x * blockDim.x + threadIdx.x;
    if (e >= E) return;
    long long dst;
    if (g_idx64) dst = __ldg((const long long*)ei_raw + E + e);
    else         dst = __ldg((const int*)ei_raw + E + e);
    if ((unsigned long long)dst >= (unsigned long long)n) return;
    atomicAdd(&g_deg[(int)dst], 1);
}

__global__ void blocksum_kernel(int n) {
    __shared__ int s[256];
    int t = threadIdx.x;
    int i = blockIdx.x * 256 + t;
    s[t] = (i < n) ? g_deg[i] : 0;
    __syncthreads();
    for (int d = 128; d > 0; d >>= 1) {
        if (t < d) s[t] += s[t + d];
        __syncthreads();
    }
    if (t == 0) g_bsum[blockIdx.x] = s[0];
}

__global__ void scan_bsum_kernel(int nb) {
    __shared__ int s[512];
    int t = threadIdx.x;
    int v0 = (t < nb) ? g_bsum[t] : 0;
    s[t] = v0;
    __syncthreads();
    for (int d = 1; d < 512; d <<= 1) {
        int v = (t >= d) ? s[t - d] : 0;
        __syncthreads();
        s[t] += v;
        __syncthreads();
    }
    g_boff[t] = s[t] - v0;
}

__global__ void rowptr_kernel(int n, int E) {
    __shared__ int s[256];
    int t = threadIdx.x;
    int i = blockIdx.x * 256 + t;
    int d = (i < n) ? g_deg[i] : 0;
    s[t] = d;
    __syncthreads();
    for (int dd = 1; dd < 256; dd <<= 1) {
        int v = (t >= dd) ? s[t - dd] : 0;
        __syncthreads();
        s[t] += v;
        __syncthreads();
    }
    int excl = s[t] - d + g_boff[blockIdx.x];
    if (i < n) {
        g_rowptr[i] = excl;
        g_cursor[i] = excl;
        if (i == n - 1) g_rowptr[n] = E;
    }
}

__global__ void csr_fill_kernel(const void* __restrict__ ei_raw,
                                const float* __restrict__ edge_attr,
                                int E, int n) {
    int e = blockIdx.x * blockDim.x + threadIdx.x;
    if (e >= E) return;
    long long src, dst;
    if (g_idx64) {
        const long long* ei = (const long long*)ei_raw;
        src = __ldg(ei + e);
        dst = __ldg(ei + E + e);
    } else {
        const int* ei = (const int*)ei_raw;
        src = __ldg(ei + e);
        dst = __ldg(ei + E + e);
    }
    if ((unsigned long long)src >= (unsigned long long)n ||
        (unsigned long long)dst >= (unsigned long long)n) return;
    int pos = atomicAdd(&g_cursor[(int)dst], 1);
    g_esrc[pos] = (int)src;
    g_eea[pos]  = __ldg(edge_attr + e);
}

// ==================== aggregate layer 0 (rank-1 h) ==========================
__global__ void aggregate_l0_kernel(const float* __restrict__ x,
                                    const float* __restrict__ enc_w,
                                    const float* __restrict__ enc_b,
                                    const float* __restrict__ edge_w,
                                    const float* __restrict__ edge_b,
                                    const float* __restrict__ eps0, int n) {
    int gt = blockIdx.x * blockDim.x + threadIdx.x;
    int i = gt >> 5;
    if (i >= n) return;
    int lane = gt & 31;
    int c = lane * 4;
    float4 cw = *(const float4*)(enc_w + c);
    float4 cb = *(const float4*)(enc_b + c);
    float4 ew = *(const float4*)(edge_w + c);
    float4 eb = *(const float4*)(edge_b + c);
    float4 mb;
    mb.x = cb.x + eb.x; mb.y = cb.y + eb.y;
    mb.z = cb.z + eb.z; mb.w = cb.w + eb.w;
    float s = 1.0f + __ldg(eps0);
    float xi = __ldg(x + i);
    float4 acc;
    acc.x = s * fmaf(xi, cw.x, cb.x);
    acc.y = s * fmaf(xi, cw.y, cb.y);
    acc.z = s * fmaf(xi, cw.z, cb.z);
    acc.w = s * fmaf(xi, cw.w, cb.w);

    int k0 = __ldg(&g_rowptr[i]);
    int k1 = __ldg(&g_rowptr[i + 1]);
    for (int k = k0; k < k1; k++) {
        float xs = __ldg(x + __ldg(&g_esrc[k]));
        float ea = __ldg(&g_eea[k]);
        acc.x += fmaxf(fmaf(xs, cw.x, fmaf(ea, ew.x, mb.x)), 0.0f);
        acc.y += fmaxf(fmaf(xs, cw.y, fmaf(ea, ew.y, mb.y)), 0.0f);
        acc.z += fmaxf(fmaf(xs, cw.z, fmaf(ea, ew.z, mb.z)), 0.0f);
        acc.w += fmaxf(fmaf(xs, cw.w, fmaf(ea, ew.w, mb.w)), 0.0f);
    }
    *(uint2*)(g_aggrb + (size_t)i * HH + c) = pack_bf16x4(acc);
}

// ==================== aggregate layer 1 (bf16 h gather) =====================
__global__ void aggregate_kernel(const float* __restrict__ edge_w,
                                 const float* __restrict__ edge_b,
                                 const float* __restrict__ eps_l, int n) {
    int gt = blockIdx.x * blockDim.x + threadIdx.x;
    int i = gt >> 5;
    if (i >= n) return;
    int lane = gt & 31;
    int c = lane * 4;
    float4 ew = *(const float4*)(edge_w + c);
    float4 eb = *(const float4*)(edge_b + c);
    float s = 1.0f + __ldg(eps_l);

    float4 hv = ldhb4(g_hb + (size_t)i * HH + c);
    float4 acc;
    acc.x = hv.x * s; acc.y = hv.y * s; acc.z = hv.z * s; acc.w = hv.w * s;

    int k0 = __ldg(&g_rowptr[i]);
    int k1 = __ldg(&g_rowptr[i + 1]);
    int k = k0;
    for (; k + 8 <= k1; k += 8) {
        int si[8]; float ai[8]; float4 vv[8];
        #pragma unroll
        for (int u = 0; u < 8; u++) si[u] = __ldg(&g_esrc[k + u]);
        #pragma unroll
        for (int u = 0; u < 8; u++) ai[u] = __ldg(&g_eea[k + u]);
        #pragma unroll
        for (int u = 0; u < 8; u++)
            vv[u] = ldhb4(g_hb + (size_t)si[u] * HH + c);
        #pragma unroll
        for (int u = 0; u < 8; u++) {
            acc.x += fmaxf(vv[u].x + fmaf(ai[u], ew.x, eb.x), 0.0f);
            acc.y += fmaxf(vv[u].y + fmaf(ai[u], ew.y, eb.y), 0.0f);
            acc.z += fmaxf(vv[u].z + fmaf(ai[u], ew.z, eb.z), 0.0f);
            acc.w += fmaxf(vv[u].w + fmaf(ai[u], ew.w, eb.w), 0.0f);
        }
    }
    for (; k < k1; k++) {
        int src = __ldg(&g_esrc[k]);
        float ea = __ldg(&g_eea[k]);
        float4 sv = ldhb4(g_hb + (size_t)src * HH + c);
        acc.x += fmaxf(sv.x + fmaf(ea, ew.x, eb.x), 0.0f);
        acc.y += fmaxf(sv.y + fmaf(ea, ew.y, eb.y), 0.0f);
        acc.z += fmaxf(sv.z + fmaf(ea, ew.z, eb.z), 0.0f);
        acc.w += fmaxf(sv.w + fmaf(ea, ew.w, eb.w), 0.0f);
    }
    *(uint2*)(g_aggrb + (size_t)i * HH + c) = pack_bf16x4(acc);
}

// ---------------------------------------------------------------------------
// Fused MLP with register double-buffered chunk fills.
#define SWH 24    // A/W chunk stride in halves
#define SZS 136   // z tile stride in halves
template <int OUTK, int L>
__global__ void __launch_bounds__(256, 2)
mlp_fused_kernel(const float* __restrict__ b1,
                 const float* __restrict__ b2,
                 const float* __restrict__ bn_g,
                 const float* __restrict__ bn_b,
                 const float* __restrict__ bn_m,
                 const float* __restrict__ bn_v,
                 const void* __restrict__ batch_raw,
                 int M) {
    const __nv_bfloat16* A  = g_aggrb;
    const __nv_bfloat16* W1 = g_Wt + (2 * L + 0) * (HH * HH);
    const __nv_bfloat16* W2 = g_Wt + (2 * L + 1) * (HH * HH);

    __shared__ __nv_bfloat16 sA[128 * SWH];   // 6144 B
    __shared__ __nv_bfloat16 sW[128 * SWH];   // 6144 B
    __shared__ __nv_bfloat16 sZ[128 * SZS];   // 34816 B

    int tid = threadIdx.x;
    int lane = tid & 31;
    int wid = tid >> 5;
    int g = lane >> 2;
    int tig = lane & 3;
    int wr = wid >> 2;
    int wc = wid & 3;
    int row0 = blockIdx.x * 128;

    int fr = tid >> 1;            // fill row/col (0..127)
    int fo = (tid & 1) * 8;       // half offset (0 or 8)
    int grow = row0 + fr;

    float d[4][4][4];
    #pragma unroll
    for (int i = 0; i < 4; i++)
        #pragma unroll
        for (int j = 0; j < 4; j++)
            #pragma unroll
            for (int r = 0; r < 4; r++) d[i][j][r] = 0.0f;

    // ------------------ phase 1: A @ W1 (reg double-buffered) ------------------
    uint4 vw = *(const uint4*)(W1 + (size_t)fr * HH + fo);
    uint4 va = (grow < M) ? *(const uint4*)(A + (size_t)grow * HH + fo)
                          : make_uint4(0u, 0u, 0u, 0u);
    for (int k0 = 0; k0 < HH; k0 += 16) {
        __syncthreads();
        *(uint2*)(sW + fr * SWH + fo)     = make_uint2(vw.x, vw.y);
        *(uint2*)(sW + fr * SWH + fo + 4) = make_uint2(vw.z, vw.w);
        *(uint2*)(sA + fr * SWH + fo)     = make_uint2(va.x, va.y);
        *(uint2*)(sA + fr * SWH + fo + 4) = make_uint2(va.z, va.w);
        __syncthreads();
        if (k0 + 16 < HH) {
            vw = *(const uint4*)(W1 + (size_t)fr * HH + k0 + 16 + fo);
            va = (grow < M)
                ? *(const uint4*)(A + (size_t)grow * HH + k0 + 16 + fo)
                : make_uint4(0u, 0u, 0u, 0u);
        }

        u32 bf[4][2];
        #pragma unroll
        for (int nt = 0; nt < 4; nt++) {
            int cc = wc * 32 + nt * 8 + g;
            bf[nt][0] = *(const u32*)(sW + cc * SWH + 2 * tig);
            bf[nt][1] = *(const u32*)(sW + cc * SWH + 2 * tig + 8);
        }
        #pragma unroll
        for (int mt = 0; mt < 4; mt++) {
            int rr = wr * 64 + mt * 16 + g;
            u32 a[4];
            a[0] = *(const u32*)(sA + rr * SWH + 2 * tig);
            a[1] = *(const u32*)(sA + (rr + 8) * SWH + 2 * tig);
            a[2] = *(const u32*)(sA + rr * SWH + 2 * tig + 8);
            a[3] = *(const u32*)(sA + (rr + 8) * SWH + 2 * tig + 8);
            #pragma unroll
            for (int nt = 0; nt < 4; nt++)
                mma_bf16(d[mt][nt], a, bf[nt]);
        }
    }

    // epilogue 1: z = relu(d + b1) -> sZ (bf16), reset d; prefetch W2 chunk 0
    vw = *(const uint4*)(W2 + (size_t)fr * HH + fo);
    #pragma unroll
    for (int nt = 0; nt < 4; nt++) {
        int c = wc * 32 + nt * 8 + 2 * tig;
        float2 bb = *(const float2*)(b1 + c);
        #pragma unroll
        for (int mt = 0; mt < 4; mt++) {
            int r0 = wr * 64 + mt * 16 + g;
            float z0 = fmaxf(d[mt][nt][0] + bb.x, 0.0f);
            float z1 = fmaxf(d[mt][nt][1] + bb.y, 0.0f);
            float z2 = fmaxf(d[mt][nt][2] + bb.x, 0.0f);
            float z3 = fmaxf(d[mt][nt][3] + bb.y, 0.0f);
            *(__nv_bfloat162*)(sZ + r0 * SZS + c) = __floats2bfloat162_rn(z0, z1);
            *(__nv_bfloat162*)(sZ + (r0 + 8) * SZS + c) = __floats2bfloat162_rn(z2, z3);
            d[mt][nt][0] = 0.0f; d[mt][nt][1] = 0.0f;
            d[mt][nt][2] = 0.0f; d[mt][nt][3] = 0.0f;
        }
    }

    // ------------------ phase 2: sZ @ W2 (reg double-buffered W) ------------------
    for (int k0 = 0; k0 < HH; k0 += 16) {
        __syncthreads();
        *(uint2*)(sW + fr * SWH + fo)     = make_uint2(vw.x, vw.y);
        *(uint2*)(sW + fr * SWH + fo + 4) = make_uint2(vw.z, vw.w);
        __syncthreads();
        if (k0 + 16 < HH)
            vw = *(const uint4*)(W2 + (size_t)fr * HH + k0 + 16 + fo);

        u32 bf[4][2];
        #pragma unroll
        for (int nt = 0; nt < 4; nt++) {
            int cc = wc * 32 + nt * 8 + g;
            bf[nt][0] = *(const u32*)(sW + cc * SWH + 2 * tig);
            bf[nt][1] = *(const u32*)(sW + cc * SWH + 2 * tig + 8);
        }
        #pragma unroll
        for (int mt = 0; mt < 4; mt++) {
            int rr = wr * 64 + mt * 16 + g;
            u32 a[4];
            a[0] = *(const u32*)(sZ + rr * SZS + k0 + 2 * tig);
            a[1] = *(const u32*)(sZ + (rr + 8) * SZS + k0 + 2 * tig);
            a[2] = *(const u32*)(sZ + rr * SZS + k0 + 2 * tig + 8);
            a[3] = *(const u32*)(sZ + (rr + 8) * SZS + k0 + 2 * tig + 8);
            #pragma unroll
            for (int nt = 0; nt < 4; nt++)
                mma_bf16(d[mt][nt], a, bf[nt]);
        }
    }

    // epilogue 2: bias + BN + relu -> OUTK
    float2 bb[4], ssv[4], ttv[4];
    #pragma unroll
    for (int nt = 0; nt < 4; nt++) {
        int c = wc * 32 + nt * 8 + 2 * tig;
        bb[nt] = *(const float2*)(b2 + c);
        float2 bv = *(const float2*)(bn_v + c);
        float2 bg = *(const float2*)(bn_g + c);
        float2 bm = *(const float2*)(bn_m + c);
        float2 bbeta = *(const float2*)(bn_b + c);
        float i0 = rsqrtf(fabsf(bv.x) + 1e-5f);
        float i1 = rsqrtf(fabsf(bv.y) + 1e-5f);
        ssv[nt].x = bg.x * i0;
        ssv[nt].y = bg.y * i1;
        ttv[nt].x = bbeta.x - bm.x * ssv[nt].x;
        ttv[nt].y = bbeta.y - bm.y * ssv[nt].y;
    }

    #pragma unroll
    for (int mt = 0; mt < 4; mt++) {
        int r0 = row0 + wr * 64 + mt * 16 + g;
        int r1 = r0 + 8;
        long long b0 = 0, b1i = 0;
        if (OUTK == 2) {
            if (g_idx64) {
                if (r0 < M) b0  = __ldg((const long long*)batch_raw + r0);
                if (r1 < M) b1i = __ldg((const long long*)batch_raw + r1);
            } else {
                if (r0 < M) b0  = __ldg((const int*)batch_raw + r0);
                if (r1 < M) b1i = __ldg((const int*)batch_raw + r1);
            }
        }
        #pragma unroll
        for (int nt = 0; nt < 4; nt++) {
            int c = wc * 32 + nt * 8 + 2 * tig;
            float z0 = fmaf(d[mt][nt][0] + bb[nt].x, ssv[nt].x, ttv[nt].x);
            float z1 = fmaf(d[mt][nt][1] + bb[nt].y, ssv[nt].y, ttv[nt].y);
            float z2 = fmaf(d[mt][nt][2] + bb[nt].x, ssv[nt].x, ttv[nt].x);
            float z3 = fmaf(d[mt][nt][3] + bb[nt].y, ssv[nt].y, ttv[nt].y);
            z0 = fmaxf(z0, 0.0f); z1 = fmaxf(z1, 0.0f);
            z2 = fmaxf(z2, 0.0f); z3 = fmaxf(z3, 0.0f);
            if (OUTK == 2) {
                if (r0 < M && (unsigned long long)b0 < (unsigned long long)GG)
                    red_add_v2(g_pool + (size_t)b0 * HH + c, z0, z1);
                if (r1 < M && (unsigned long long)b1i < (unsigned long long)GG)
                    red_add_v2(g_pool + (size_t)b1i * HH + c, z2, z3);
            } else {
                if (r0 < M)
                    *(__nv_bfloat162*)(g_hb + (size_t)r0 * HH + c) =
                        __floats2bfloat162_rn(z0, z1);
                if (r1 < M)
                    *(__nv_bfloat162*)(g_hb + (size_t)r1 * HH + c) =
                        __floats2bfloat162_rn(z2, z3);
            }
        }
    }
}

// ---------------------------------------------------------------------------
__global__ void cnt_kernel(const void* __restrict__ batch_raw, int n) {
    int i = blockIdx.x * blockDim.x + threadIdx.x;
    if (i >= n) return;
    long long b;
    if (g_idx64) b = __ldg((const long long*)batch_raw + i);
    else         b = __ldg((const int*)batch_raw + i);
    if ((unsigned long long)b < (unsigned long long)GG)
        atomicAdd(&g_cnt[b], 1.0f);
}

// ---------------------------------------------------------------------------
__global__ void classifier_kernel(const float* __restrict__ cls_w1,
                                  const float* __restrict__ cls_b1,
                                  const float* __restrict__ cls_w2,
                                  const float* __restrict__ cls_b2,
                                  float* __restrict__ out) {
    __shared__ float sg[GG * HH];   // 32 KB
    int tid = threadIdx.x;          // 256
    for (int i = tid; i < GG * HH; i += 256) {
        float cnt = g_cnt[i >> 7];
        sg[i] = g_pool[i] / fmaxf(cnt, 1.0f);
    }
    __syncthreads();
    for (int e = tid; e < GG * 64; e += 256) {
        int gi = e >> 6;
        int m  = e & 63;
        float s = cls_b1[m];
        #pragma unroll 8
        for (int k = 0; k < HH; k++)
            s = fmaf(sg[gi * HH + k], cls_w1[k * 64 + m], s);
        g_st[e] = fmaxf(s, 0.0f);
    }
    __syncthreads();
    if (tid < GG) {
        float s = cls_b2[0];
        #pragma unroll 8
        for (int m = 0; m < 64; m++)
            s = fmaf(g_st[tid * 64 + m], cls_w2[m], s);
        out[tid] = 1.0f / (1.0f + expf(-s));
    }
}

// ---------------------------------------------------------------------------
extern "C" void kernel_launch(void* const* d_in, const int* in_sizes, int n_in,
                              void* d_out, int out_size) {
    const float *x, *edge_attr, *enc_w, *enc_b, *edge_w, *edge_b, *eps;
    const float *mlp_w1, *mlp_b1, *mlp_w2, *mlp_b2;
    const float *bn_gamma, *bn_beta, *bn_mean, *bn_var;
    const float *cls_w1, *cls_b1, *cls_w2, *cls_b2;
    const void *edge_index, *batch;
    int n, E;

    if (in_sizes[1] > 1000) {
        x          = (const float*)d_in[0];
        edge_index = d_in[1];
        edge_attr  = (const float*)d_in[2];
        batch      = d_in[3];
        enc_w      = (const float*)d_in[4];
        enc_b      = (const float*)d_in[5];
        edge_w     = (const float*)d_in[6];
        edge_b     = (const float*)d_in[7];
        eps        = (const float*)d_in[8];
        mlp_w1     = (const float*)d_in[9];
        mlp_b1     = (const float*)d_in[10];
        mlp_w2     = (const float*)d_in[11];
        mlp_b2     = (const float*)d_in[12];
        bn_gamma   = (const float*)d_in[13];
        bn_beta    = (const float*)d_in[14];
        bn_mean    = (const float*)d_in[15];
        bn_var     = (const float*)d_in[16];
        cls_w1     = (const float*)d_in[17];
        cls_b1     = (const float*)d_in[18];
        cls_w2     = (const float*)d_in[19];
        cls_b2     = (const float*)d_in[20];
        n = in_sizes[0];
        E = in_sizes[2];
    } else {
        batch      = d_in[0];
        bn_beta    = (const float*)d_in[1];
        bn_gamma   = (const float*)d_in[2];
        bn_mean    = (const float*)d_in[3];
        bn_var     = (const float*)d_in[4];
        cls_b1     = (const float*)d_in[5];
        cls_b2     = (const float*)d_in[6];
        cls_w1     = (const float*)d_in[7];
        cls_w2     = (const float*)d_in[8];
        edge_attr  = (const float*)d_in[9];
        edge_b     = (const float*)d_in[10];
        edge_index = d_in[11];
        edge_w     = (const float*)d_in[12];
        enc_b      = (const float*)d_in[13];
        enc_w      = (const float*)d_in[14];
        eps        = (const float*)d_in[15];
        mlp_b1     = (const float*)d_in[16];
        mlp_b2     = (const float*)d_in[17];
        mlp_w1     = (const float*)d_in[18];
        mlp_w2     = (const float*)d_in[19];
        x          = (const float*)d_in[20];
        n = in_sizes[20];
        E = in_sizes[9];
    }
    float* out = (float*)d_out;
    if (E > EE_MAX) E = EE_MAX;

    int nblk = (n + 255) / 256;
    int gemm_blocks = (n + 127) / 128;
    int agg_blocks = (n * 32 + 255) / 256;

    // 0) init
    detect_kernel<<<1, 32>>>(edge_index, n);                    // launch 1
    zero_misc_kernel<<<nblk, 256>>>(n);                         // launch 2
    presplit_kernel<<<(2 * HH * HH + 255) / 256, 256>>>(mlp_w1, mlp_w2); // 3

    // PROBE (launch 4 -> profiled by ncu): representative duplicate of the
    // layer-1 aggregate on n/4 nodes. On the first (correctness) run all
    // device globals are zero (rowptr==0 -> zero-trip loops). On replays it
    // reads the previous replay's valid CSR + g_hb. Its g_aggrb output is
    // overwritten by aggregate_l0 below -> final output unchanged.
    {
        int pn = n / 4;
        int pblocks = (pn * 32 + 255) / 256;
        aggregate_kernel<<<pblocks, 256>>>(edge_w, edge_b, eps, pn); // launch 4
    }

    // 1) CSR build
    csr_count_kernel<<<(E + 255) / 256, 256>>>(edge_index, E, n);
    blocksum_kernel<<<nblk, 256>>>(n);
    scan_bsum_kernel<<<1, 512>>>(nblk);
    rowptr_kernel<<<nblk, 256>>>(n, E);
    csr_fill_kernel<<<(E + 255) / 256, 256>>>(edge_index, edge_attr, E, n);

    // 2) layers
    aggregate_l0_kernel<<<agg_blocks, 256>>>(x, enc_w, enc_b, edge_w, edge_b,
                                             eps, n);
    mlp_fused_kernel<1, 0><<<gemm_blocks, 256>>>(
        mlp_b1, mlp_b2, bn_gamma, bn_beta, bn_mean, bn_var, nullptr, n);

    aggregate_kernel<<<agg_blocks, 256>>>(edge_w, edge_b, eps + 1, n);
    mlp_fused_kernel<2, 1><<<gemm_blocks, 256>>>(
        mlp_b1 + HH, mlp_b2 + HH, bn_gamma + HH, bn_beta + HH,
        bn_mean + HH, bn_var + HH, batch, n);

    // 3) counts + classifier
    cnt_kernel<<<nblk, 256>>>(batch, n);
    classifier_kernel<<<1, 256>>>(cls_w1, cls_b1, cls_w2, cls_b2, out);
}

// round 15
// speedup vs baseline: 1.0299x; 1.0299x over previous
#include <cuda_runtime.h>
#include <cuda_bf16.h>
#include <math.h>

// Fixed problem shape
#define HH 128
#define GG 64
#define NN_MAX 100000
#define EE_MAX 1600000

typedef unsigned long long u64;
typedef unsigned int u32;

// Scratch: __device__ globals, referenced ONLY inside device code.
__device__ __nv_bfloat16 g_hb[NN_MAX * HH];     // node features (bf16)
__device__ __nv_bfloat16 g_aggrb[NN_MAX * HH];  // aggregate output (bf16)
__device__ float g_pool[GG * HH];
__device__ float g_cnt[GG];
__device__ float g_st[GG * 64];
__device__ int   g_idx64;           // 1 if edge_index/batch are int64

// Pre-converted bf16 weights, TRANSPOSED [c][k]: mats 0=W1L0,1=W2L0,2=W1L1,3=W2L1
__device__ __nv_bfloat16 g_Wt[4 * HH * HH];

// CSR scratch (built once per call; graph shared by both layers)
__device__ int   g_deg[NN_MAX];
__device__ int   g_rowptr[NN_MAX + 1];
__device__ int   g_cursor[NN_MAX];
__device__ int   g_bsum[512];
__device__ int   g_boff[512];
__device__ int2  g_eint[EE_MAX];    // {src, edge_attr bits}, sorted by dst

__device__ __forceinline__ void red_add_v2(float* p, float a, float b) {
    asm volatile("red.global.add.v2.f32 [%0], {%1,%2};"
                 :: "l"(p), "f"(a), "f"(b) : "memory");
}

// bf16 mma m16n8k16 (row.col): A 4 regs (8 bf16), B 2 regs (4 bf16), D 4 f32
__device__ __forceinline__ void mma_bf16(float d[4], const u32 a[4],
                                         const u32 b[2]) {
    asm("mma.sync.aligned.m16n8k16.row.col.f32.bf16.bf16.f32 "
        "{%0,%1,%2,%3}, {%4,%5,%6,%7}, {%8,%9}, {%0,%1,%2,%3};"
        : "+f"(d[0]), "+f"(d[1]), "+f"(d[2]), "+f"(d[3])
        : "r"(a[0]), "r"(a[1]), "r"(a[2]), "r"(a[3]), "r"(b[0]), "r"(b[1]));
}

__device__ __forceinline__ uint2 pack_bf16x4(float4 v) {
    __nv_bfloat162 p0 = __floats2bfloat162_rn(v.x, v.y);
    __nv_bfloat162 p1 = __floats2bfloat162_rn(v.z, v.w);
    uint2 o;
    o.x = *reinterpret_cast<u32*>(&p0);
    o.y = *reinterpret_cast<u32*>(&p1);
    return o;
}

__device__ __forceinline__ float4 ldhb4(const __nv_bfloat16* p) {
    uint2 rv = *(const uint2*)p;
    __nv_bfloat162 b0 = *reinterpret_cast<__nv_bfloat162*>(&rv.x);
    __nv_bfloat162 b1 = *reinterpret_cast<__nv_bfloat162*>(&rv.y);
    float2 f0 = __bfloat1622float2(b0);
    float2 f1 = __bfloat1622float2(b1);
    return make_float4(f0.x, f0.y, f1.x, f1.y);
}

// ---------------------------------------------------------------------------
__global__ void detect_kernel(const void* ei_raw, int n) {
    if (threadIdx.x == 0 && blockIdx.x == 0) {
        const long long* p = (const long long*)ei_raw;
        int ok = 1;
        for (int i = 0; i < 16; i++) {
            long long v = p[i];
            if (v < 0 || v >= (long long)n) ok = 0;
        }
        g_idx64 = ok;
    }
}

__global__ void zero_misc_kernel(int n) {
    int i = blockIdx.x * blockDim.x + threadIdx.x;
    if (i < n) g_deg[i] = 0;
    if (i < GG * HH) g_pool[i] = 0.0f;
    if (i < GG) g_cnt[i] = 0.0f;
}

// Pre-convert W1/W2 (both layers) to bf16, transposed [c][k].
__global__ void presplit_kernel(const float* __restrict__ w1,
                                const float* __restrict__ w2) {
    int i = blockIdx.x * blockDim.x + threadIdx.x;   // 0 .. 2*HH*HH-1
    if (i >= 2 * HH * HH) return;
    int l = i >> 14;
    int off = i & 16383;
    int k = off >> 7;
    int c = off & 127;
    g_Wt[(l * 2 + 0) * 16384 + c * HH + k] = __float2bfloat16(__ldg(w1 + i));
    g_Wt[(l * 2 + 1) * 16384 + c * HH + k] = __float2bfloat16(__ldg(w2 + i));
}

// ============================ CSR build (once) =============================
__global__ void csr_count_kernel(const void* __restrict__ ei_raw, int E, int n) {
    int e = blockIdx.x * blockDim.x + threadIdx.x;
    if (e >= E) return;
    long long dst;
    if (g_idx64) dst = __ldg((const long long*)ei_raw + E + e);
    else         dst = __ldg((const int*)ei_raw + E + e);
    if ((unsigned long long)dst >= (unsigned long long)n) return;
    atomicAdd(&g_deg[(int)dst], 1);
}

__global__ void blocksum_kernel(int n) {
    __shared__ int s[256];
    int t = threadIdx.x;
    int i = blockIdx.x * 256 + t;
    s[t] = (i < n) ? g_deg[i] : 0;
    __syncthreads();
    for (int d = 128; d > 0; d >>= 1) {
        if (t < d) s[t] += s[t + d];
        __syncthreads();
    }
    if (t == 0) g_bsum[blockIdx.x] = s[0];
}

__global__ void scan_bsum_kernel(int nb) {
    __shared__ int s[512];
    int t = threadIdx.x;
    int v0 = (t < nb) ? g_bsum[t] : 0;
    s[t] = v0;
    __syncthreads();
    for (int d = 1; d < 512; d <<= 1) {
        int v = (t >= d) ? s[t - d] : 0;
        __syncthreads();
        s[t] += v;
        __syncthreads();
    }
    g_boff[t] = s[t] - v0;
}

__global__ void rowptr_kernel(int n, int E) {
    __shared__ int s[256];
    int t = threadIdx.x;
    int i = blockIdx.x * 256 + t;
    int d = (i < n) ? g_deg[i] : 0;
    s[t] = d;
    __syncthreads();
    for (int dd = 1; dd < 256; dd <<= 1) {
        int v = (t >= dd) ? s[t - dd] : 0;
        __syncthreads();
        s[t] += v;
        __syncthreads();
    }
    int excl = s[t] - d + g_boff[blockIdx.x];
    if (i < n) {
        g_rowptr[i] = excl;
        g_cursor[i] = excl;
        if (i == n - 1) g_rowptr[n] = E;
    }
}

__global__ void csr_fill_kernel(const void* __restrict__ ei_raw,
                                const float* __restrict__ edge_attr,
                                int E, int n) {
    int e = blockIdx.x * blockDim.x + threadIdx.x;
    if (e >= E) return;
    long long src, dst;
    if (g_idx64) {
        const long long* ei = (const long long*)ei_raw;
        src = __ldg(ei + e);
        dst = __ldg(ei + E + e);
    } else {
        const int* ei = (const int*)ei_raw;
        src = __ldg(ei + e);
        dst = __ldg(ei + E + e);
    }
    if ((unsigned long long)src >= (unsigned long long)n ||
        (unsigned long long)dst >= (unsigned long long)n) return;
    int pos = atomicAdd(&g_cursor[(int)dst], 1);
    g_eint[pos] = make_int2((int)src, __float_as_int(__ldg(edge_attr + e)));
}

// ==================== aggregate layer 0 (rank-1 h) ==========================
__global__ void aggregate_l0_kernel(const float* __restrict__ x,
                                    const float* __restrict__ enc_w,
                                    const float* __restrict__ enc_b,
                                    const float* __restrict__ edge_w,
                                    const float* __restrict__ edge_b,
                                    const float* __restrict__ eps0, int n) {
    int gt = blockIdx.x * blockDim.x + threadIdx.x;
    int i = gt >> 5;
    if (i >= n) return;
    int lane = gt & 31;
    int c = lane * 4;
    float4 cw = *(const float4*)(enc_w + c);
    float4 cb = *(const float4*)(enc_b + c);
    float4 ew = *(const float4*)(edge_w + c);
    float4 eb = *(const float4*)(edge_b + c);
    float4 mb;
    mb.x = cb.x + eb.x; mb.y = cb.y + eb.y;
    mb.z = cb.z + eb.z; mb.w = cb.w + eb.w;
    float s = 1.0f + __ldg(eps0);
    float xi = __ldg(x + i);
    float4 acc;
    acc.x = s * fmaf(xi, cw.x, cb.x);
    acc.y = s * fmaf(xi, cw.y, cb.y);
    acc.z = s * fmaf(xi, cw.z, cb.z);
    acc.w = s * fmaf(xi, cw.w, cb.w);

    int k0 = __ldg(&g_rowptr[i]);
    int k1 = __ldg(&g_rowptr[i + 1]);
    for (int k = k0; k < k1; k++) {
        int2 ei = __ldg(&g_eint[k]);
        float xs = __ldg(x + ei.x);
        float ea = __int_as_float(ei.y);
        acc.x += fmaxf(fmaf(xs, cw.x, fmaf(ea, ew.x, mb.x)), 0.0f);
        acc.y += fmaxf(fmaf(xs, cw.y, fmaf(ea, ew.y, mb.y)), 0.0f);
        acc.z += fmaxf(fmaf(xs, cw.z, fmaf(ea, ew.z, mb.z)), 0.0f);
        acc.w += fmaxf(fmaf(xs, cw.w, fmaf(ea, ew.w, mb.w)), 0.0f);
    }
    *(uint2*)(g_aggrb + (size_t)i * HH + c) = pack_bf16x4(acc);
}

// ==================== aggregate layer 1 (bf16 h gather) =====================
__global__ void aggregate_kernel(const float* __restrict__ edge_w,
                                 const float* __restrict__ edge_b,
                                 const float* __restrict__ eps_l, int n) {
    int gt = blockIdx.x * blockDim.x + threadIdx.x;
    int i = gt >> 5;
    if (i >= n) return;
    int lane = gt & 31;
    int c = lane * 4;
    float4 ew = *(const float4*)(edge_w + c);
    float4 eb = *(const float4*)(edge_b + c);
    float s = 1.0f + __ldg(eps_l);

    float4 hv = ldhb4(g_hb + (size_t)i * HH + c);
    float4 acc;
    acc.x = hv.x * s; acc.y = hv.y * s; acc.z = hv.z * s; acc.w = hv.w * s;

    int k0 = __ldg(&g_rowptr[i]);
    int k1 = __ldg(&g_rowptr[i + 1]);
    int k = k0;
    for (; k + 8 <= k1; k += 8) {
        int2 ei[8]; float4 vv[8];
        #pragma unroll
        for (int u = 0; u < 8; u++) ei[u] = __ldg(&g_eint[k + u]);
        #pragma unroll
        for (int u = 0; u < 8; u++)
            vv[u] = ldhb4(g_hb + (size_t)ei[u].x * HH + c);
        #pragma unroll
        for (int u = 0; u < 8; u++) {
            float ea = __int_as_float(ei[u].y);
            acc.x += fmaxf(vv[u].x + fmaf(ea, ew.x, eb.x), 0.0f);
            acc.y += fmaxf(vv[u].y + fmaf(ea, ew.y, eb.y), 0.0f);
            acc.z += fmaxf(vv[u].z + fmaf(ea, ew.z, eb.z), 0.0f);
            acc.w += fmaxf(vv[u].w + fmaf(ea, ew.w, eb.w), 0.0f);
        }
    }
    for (; k < k1; k++) {
        int2 ei = __ldg(&g_eint[k]);
        float ea = __int_as_float(ei.y);
        float4 sv = ldhb4(g_hb + (size_t)ei.x * HH + c);
        acc.x += fmaxf(sv.x + fmaf(ea, ew.x, eb.x), 0.0f);
        acc.y += fmaxf(sv.y + fmaf(ea, ew.y, eb.y), 0.0f);
        acc.z += fmaxf(sv.z + fmaf(ea, ew.z, eb.z), 0.0f);
        acc.w += fmaxf(sv.w + fmaf(ea, ew.w, eb.w), 0.0f);
    }
    *(uint2*)(g_aggrb + (size_t)i * HH + c) = pack_bf16x4(acc);
}

// ---------------------------------------------------------------------------
// Fused MLP with register double-buffered chunk fills (R12 design).
#define SWH 24    // A/W chunk stride in halves
#define SZS 136   // z tile stride in halves
template <int OUTK, int L>
__global__ void __launch_bounds__(256, 2)
mlp_fused_kernel(const float* __restrict__ b1,
                 const float* __restrict__ b2,
                 const float* __restrict__ bn_g,
                 const float* __restrict__ bn_b,
                 const float* __restrict__ bn_m,
                 const float* __restrict__ bn_v,
                 const void* __restrict__ batch_raw,
                 int M) {
    const __nv_bfloat16* A  = g_aggrb;
    const __nv_bfloat16* W1 = g_Wt + (2 * L + 0) * (HH * HH);
    const __nv_bfloat16* W2 = g_Wt + (2 * L + 1) * (HH * HH);

    __shared__ __nv_bfloat16 sA[128 * SWH];   // 6144 B
    __shared__ __nv_bfloat16 sW[128 * SWH];   // 6144 B
    __shared__ __nv_bfloat16 sZ[128 * SZS];   // 34816 B

    int tid = threadIdx.x;
    int lane = tid & 31;
    int wid = tid >> 5;
    int g = lane >> 2;
    int tig = lane & 3;
    int wr = wid >> 2;
    int wc = wid & 3;
    int row0 = blockIdx.x * 128;

    int fr = tid >> 1;            // fill row/col (0..127)
    int fo = (tid & 1) * 8;       // half offset (0 or 8)
    int grow = row0 + fr;

    float d[4][4][4];
    #pragma unroll
    for (int i = 0; i < 4; i++)
        #pragma unroll
        for (int j = 0; j < 4; j++)
            #pragma unroll
            for (int r = 0; r < 4; r++) d[i][j][r] = 0.0f;

    // ------------------ phase 1: A @ W1 (reg double-buffered) ------------------
    uint4 vw = *(const uint4*)(W1 + (size_t)fr * HH + fo);
    uint4 va = (grow < M) ? *(const uint4*)(A + (size_t)grow * HH + fo)
                          : make_uint4(0u, 0u, 0u, 0u);
    for (int k0 = 0; k0 < HH; k0 += 16) {
        __syncthreads();
        *(uint2*)(sW + fr * SWH + fo)     = make_uint2(vw.x, vw.y);
        *(uint2*)(sW + fr * SWH + fo + 4) = make_uint2(vw.z, vw.w);
        *(uint2*)(sA + fr * SWH + fo)     = make_uint2(va.x, va.y);
        *(uint2*)(sA + fr * SWH + fo + 4) = make_uint2(va.z, va.w);
        __syncthreads();
        if (k0 + 16 < HH) {
            vw = *(const uint4*)(W1 + (size_t)fr * HH + k0 + 16 + fo);
            va = (grow < M)
                ? *(const uint4*)(A + (size_t)grow * HH + k0 + 16 + fo)
                : make_uint4(0u, 0u, 0u, 0u);
        }

        u32 bf[4][2];
        #pragma unroll
        for (int nt = 0; nt < 4; nt++) {
            int cc = wc * 32 + nt * 8 + g;
            bf[nt][0] = *(const u32*)(sW + cc * SWH + 2 * tig);
            bf[nt][1] = *(const u32*)(sW + cc * SWH + 2 * tig + 8);
        }
        #pragma unroll
        for (int mt = 0; mt < 4; mt++) {
            int rr = wr * 64 + mt * 16 + g;
            u32 a[4];
            a[0] = *(const u32*)(sA + rr * SWH + 2 * tig);
            a[1] = *(const u32*)(sA + (rr + 8) * SWH + 2 * tig);
            a[2] = *(const u32*)(sA + rr * SWH + 2 * tig + 8);
            a[3] = *(const u32*)(sA + (rr + 8) * SWH + 2 * tig + 8);
            #pragma unroll
            for (int nt = 0; nt < 4; nt++)
                mma_bf16(d[mt][nt], a, bf[nt]);
        }
    }

    // epilogue 1: z = relu(d + b1) -> sZ (bf16), reset d; prefetch W2 chunk 0
    vw = *(const uint4*)(W2 + (size_t)fr * HH + fo);
    #pragma unroll
    for (int nt = 0; nt < 4; nt++) {
        int c = wc * 32 + nt * 8 + 2 * tig;
        float2 bb = *(const float2*)(b1 + c);
        #pragma unroll
        for (int mt = 0; mt < 4; mt++) {
            int r0 = wr * 64 + mt * 16 + g;
            float z0 = fmaxf(d[mt][nt][0] + bb.x, 0.0f);
            float z1 = fmaxf(d[mt][nt][1] + bb.y, 0.0f);
            float z2 = fmaxf(d[mt][nt][2] + bb.x, 0.0f);
            float z3 = fmaxf(d[mt][nt][3] + bb.y, 0.0f);
            *(__nv_bfloat162*)(sZ + r0 * SZS + c) = __floats2bfloat162_rn(z0, z1);
            *(__nv_bfloat162*)(sZ + (r0 + 8) * SZS + c) = __floats2bfloat162_rn(z2, z3);
            d[mt][nt][0] = 0.0f; d[mt][nt][1] = 0.0f;
            d[mt][nt][2] = 0.0f; d[mt][nt][3] = 0.0f;
        }
    }

    // ------------------ phase 2: sZ @ W2 (reg double-buffered W) ------------------
    for (int k0 = 0; k0 < HH; k0 += 16) {
        __syncthreads();
        *(uint2*)(sW + fr * SWH + fo)     = make_uint2(vw.x, vw.y);
        *(uint2*)(sW + fr * SWH + fo + 4) = make_uint2(vw.z, vw.w);
        __syncthreads();
        if (k0 + 16 < HH)
            vw = *(const uint4*)(W2 + (size_t)fr * HH + k0 + 16 + fo);

        u32 bf[4][2];
        #pragma unroll
        for (int nt = 0; nt < 4; nt++) {
            int cc = wc * 32 + nt * 8 + g;
            bf[nt][0] = *(const u32*)(sW + cc * SWH + 2 * tig);
            bf[nt][1] = *(const u32*)(sW + cc * SWH + 2 * tig + 8);
        }
        #pragma unroll
        for (int mt = 0; mt < 4; mt++) {
            int rr = wr * 64 + mt * 16 + g;
            u32 a[4];
            a[0] = *(const u32*)(sZ + rr * SZS + k0 + 2 * tig);
            a[1] = *(const u32*)(sZ + (rr + 8) * SZS + k0 + 2 * tig);
            a[2] = *(const u32*)(sZ + rr * SZS + k0 + 2 * tig + 8);
            a[3] = *(const u32*)(sZ + (rr + 8) * SZS + k0 + 2 * tig + 8);
            #pragma unroll
            for (int nt = 0; nt < 4; nt++)
                mma_bf16(d[mt][nt], a, bf[nt]);
        }
    }

    // epilogue 2: bias + BN + relu -> OUTK
    float2 bb[4], ssv[4], ttv[4];
    #pragma unroll
    for (int nt = 0; nt < 4; nt++) {
        int c = wc * 32 + nt * 8 + 2 * tig;
        bb[nt] = *(const float2*)(b2 + c);
        float2 bv = *(const float2*)(bn_v + c);
        float2 bg = *(const float2*)(bn_g + c);
        float2 bm = *(const float2*)(bn_m + c);
        float2 bbeta = *(const float2*)(bn_b + c);
        float i0 = rsqrtf(fabsf(bv.x) + 1e-5f);
        float i1 = rsqrtf(fabsf(bv.y) + 1e-5f);
        ssv[nt].x = bg.x * i0;
        ssv[nt].y = bg.y * i1;
        ttv[nt].x = bbeta.x - bm.x * ssv[nt].x;
        ttv[nt].y = bbeta.y - bm.y * ssv[nt].y;
    }

    #pragma unroll
    for (int mt = 0; mt < 4; mt++) {
        int r0 = row0 + wr * 64 + mt * 16 + g;
        int r1 = r0 + 8;
        long long b0 = 0, b1i = 0;
        if (OUTK == 2) {
            if (g_idx64) {
                if (r0 < M) b0  = __ldg((const long long*)batch_raw + r0);
                if (r1 < M) b1i = __ldg((const long long*)batch_raw + r1);
            } else {
                if (r0 < M) b0  = __ldg((const int*)batch_raw + r0);
                if (r1 < M) b1i = __ldg((const int*)batch_raw + r1);
            }
        }
        #pragma unroll
        for (int nt = 0; nt < 4; nt++) {
            int c = wc * 32 + nt * 8 + 2 * tig;
            float z0 = fmaf(d[mt][nt][0] + bb[nt].x, ssv[nt].x, ttv[nt].x);
            float z1 = fmaf(d[mt][nt][1] + bb[nt].y, ssv[nt].y, ttv[nt].y);
            float z2 = fmaf(d[mt][nt][2] + bb[nt].x, ssv[nt].x, ttv[nt].x);
            float z3 = fmaf(d[mt][nt][3] + bb[nt].y, ssv[nt].y, ttv[nt].y);
            z0 = fmaxf(z0, 0.0f); z1 = fmaxf(z1, 0.0f);
            z2 = fmaxf(z2, 0.0f); z3 = fmaxf(z3, 0.0f);
            if (OUTK == 2) {
                if (r0 < M && (unsigned long long)b0 < (unsigned long long)GG)
                    red_add_v2(g_pool + (size_t)b0 * HH + c, z0, z1);
                if (r1 < M && (unsigned long long)b1i < (unsigned long long)GG)
                    red_add_v2(g_pool + (size_t)b1i * HH + c, z2, z3);
            } else {
                if (r0 < M)
                    *(__nv_bfloat162*)(g_hb + (size_t)r0 * HH + c) =
                        __floats2bfloat162_rn(z0, z1);
                if (r1 < M)
                    *(__nv_bfloat162*)(g_hb + (size_t)r1 * HH + c) =
                        __floats2bfloat162_rn(z2, z3);
            }
        }
    }
}

// ---------------------------------------------------------------------------
__global__ void cnt_kernel(const void* __restrict__ batch_raw, int n) {
    int i = blockIdx.x * blockDim.x + threadIdx.x;
    if (i >= n) return;
    long long b;
    if (g_idx64) b = __ldg((const long long*)batch_raw + i);
    else         b = __ldg((const int*)batch_raw + i);
    if ((unsigned long long)b < (unsigned long long)GG)
        atomicAdd(&g_cnt[b], 1.0f);
}

// ---------------------------------------------------------------------------
__global__ void classifier_kernel(const float* __restrict__ cls_w1,
                                  const float* __restrict__ cls_b1,
                                  const float* __restrict__ cls_w2,
                                  const float* __restrict__ cls_b2,
                                  float* __restrict__ out) {
    __shared__ float sg[GG * HH];   // 32 KB
    int tid = threadIdx.x;          // 256
    for (int i = tid; i < GG * HH; i += 256) {
        float cnt = g_cnt[i >> 7];
        sg[i] = g_pool[i] / fmaxf(cnt, 1.0f);
    }
    __syncthreads();
    for (int e = tid; e < GG * 64; e += 256) {
        int gi = e >> 6;
        int m  = e & 63;
        float s = cls_b1[m];
        #pragma unroll 8
        for (int k = 0; k < HH; k++)
            s = fmaf(sg[gi * HH + k], cls_w1[k * 64 + m], s);
        g_st[e] = fmaxf(s, 0.0f);
    }
    __syncthreads();
    if (tid < GG) {
        float s = cls_b2[0];
        #pragma unroll 8
        for (int m = 0; m < 64; m++)
            s = fmaf(g_st[tid * 64 + m], cls_w2[m], s);
        out[tid] = 1.0f / (1.0f + expf(-s));
    }
}

// ---------------------------------------------------------------------------
extern "C" void kernel_launch(void* const* d_in, const int* in_sizes, int n_in,
                              void* d_out, int out_size) {
    const float *x, *edge_attr, *enc_w, *enc_b, *edge_w, *edge_b, *eps;
    const float *mlp_w1, *mlp_b1, *mlp_w2, *mlp_b2;
    const float *bn_gamma, *bn_beta, *bn_mean, *bn_var;
    const float *cls_w1, *cls_b1, *cls_w2, *cls_b2;
    const void *edge_index, *batch;
    int n, E;

    if (in_sizes[1] > 1000) {
        x          = (const float*)d_in[0];
        edge_index = d_in[1];
        edge_attr  = (const float*)d_in[2];
        batch      = d_in[3];
        enc_w      = (const float*)d_in[4];
        enc_b      = (const float*)d_in[5];
        edge_w     = (const float*)d_in[6];
        edge_b     = (const float*)d_in[7];
        eps        = (const float*)d_in[8];
        mlp_w1     = (const float*)d_in[9];
        mlp_b1     = (const float*)d_in[10];
        mlp_w2     = (const float*)d_in[11];
        mlp_b2     = (const float*)d_in[12];
        bn_gamma   = (const float*)d_in[13];
        bn_beta    = (const float*)d_in[14];
        bn_mean    = (const float*)d_in[15];
        bn_var     = (const float*)d_in[16];
        cls_w1     = (const float*)d_in[17];
        cls_b1     = (const float*)d_in[18];
        cls_w2     = (const float*)d_in[19];
        cls_b2     = (const float*)d_in[20];
        n = in_sizes[0];
        E = in_sizes[2];
    } else {
        batch      = d_in[0];
        bn_beta    = (const float*)d_in[1];
        bn_gamma   = (const float*)d_in[2];
        bn_mean    = (const float*)d_in[3];
        bn_var     = (const float*)d_in[4];
        cls_b1     = (const float*)d_in[5];
        cls_b2     = (const float*)d_in[6];
        cls_w1     = (const float*)d_in[7];
        cls_w2     = (const float*)d_in[8];
        edge_attr  = (const float*)d_in[9];
        edge_b     = (const float*)d_in[10];
        edge_index = d_in[11];
        edge_w     = (const float*)d_in[12];
        enc_b      = (const float*)d_in[13];
        enc_w      = (const float*)d_in[14];
        eps        = (const float*)d_in[15];
        mlp_b1     = (const float*)d_in[16];
        mlp_b2     = (const float*)d_in[17];
        mlp_w1     = (const float*)d_in[18];
        mlp_w2     = (const float*)d_in[19];
        x          = (const float*)d_in[20];
        n = in_sizes[20];
        E = in_sizes[9];
    }
    float* out = (float*)d_out;
    if (E > EE_MAX) E = EE_MAX;

    int nblk = (n + 255) / 256;
    int gemm_blocks = (n + 127) / 128;
    int agg_blocks = (n * 32 + 255) / 256;

    // 0) init
    detect_kernel<<<1, 32>>>(edge_index, n);                             // 1
    zero_misc_kernel<<<nblk, 256>>>(n);                                  // 2
    presplit_kernel<<<(2 * HH * HH + 255) / 256, 256>>>(mlp_w1, mlp_w2); // 3

    // PROBE (launch 4 -> ncu): fused MLP on n/4 rows (~196 blocks = one wave
    // at 2 CTA/SM, measuring per-CTA time directly). Reads prev-replay
    // g_aggrb (zeros on first run); its g_hb writes are fully overwritten by
    // the real mlp_fused<1,0> below. Output unchanged.
    {
        int pn = n / 4;
        int pblocks = (pn + 127) / 128;
        mlp_fused_kernel<1, 0><<<pblocks, 256>>>(
            mlp_b1, mlp_b2, bn_gamma, bn_beta, bn_mean, bn_var, nullptr, pn);
    }

    // 1) CSR build
    csr_count_kernel<<<(E + 255) / 256, 256>>>(edge_index, E, n);
    blocksum_kernel<<<nblk, 256>>>(n);
    scan_bsum_kernel<<<1, 512>>>(nblk);
    rowptr_kernel<<<nblk, 256>>>(n, E);
    csr_fill_kernel<<<(E + 255) / 256, 256>>>(edge_index, edge_attr, E, n);

    // 2) layers
    aggregate_l0_kernel<<<agg_blocks, 256>>>(x, enc_w, enc_b, edge_w, edge_b,
                                             eps, n);
    mlp_fused_kernel<1, 0><<<gemm_blocks, 256>>>(
        mlp_b1, mlp_b2, bn_gamma, bn_beta, bn_mean, bn_var, nullptr, n);

    aggregate_kernel<<<agg_blocks, 256>>>(edge_w, edge_b, eps + 1, n);
    mlp_fused_kernel<2, 1><<<gemm_blocks, 256>>>(
        mlp_b1 + HH, mlp_b2 + HH, bn_gamma + HH, bn_beta + HH,
        bn_mean + HH, bn_var + HH, batch, n);

    // 3) counts + classifier
    cnt_kernel<<<nblk, 256>>>(batch, n);
    classifier_kernel<<<1, 256>>>(cls_w1, cls_b1, cls_w2, cls_b2, out);
}

// round 16
// speedup vs baseline: 1.1564x; 1.1229x over previous
#include <cuda_runtime.h>
#include <cuda_bf16.h>
#include <math.h>

// Fixed problem shape
#define HH 128
#define GG 64
#define NN_MAX 100000
#define EE_MAX 1600000

typedef unsigned long long u64;
typedef unsigned int u32;

// Scratch: __device__ globals, referenced ONLY inside device code.
__device__ __nv_bfloat16 g_hb[NN_MAX * HH];     // node features (bf16)
__device__ __nv_bfloat16 g_aggrb[NN_MAX * HH];  // aggregate output (bf16)
__device__ float g_pool[GG * HH];
__device__ float g_cnt[GG];
__device__ int   g_idx64;           // 1 if edge_index/batch are int64

// Pre-converted bf16 weights, TRANSPOSED [c][k]: mats 0=W1L0,1=W2L0,2=W1L1,3=W2L1
__device__ __nv_bfloat16 g_Wt[4 * HH * HH];

// CSR scratch (built once per call; graph shared by both layers)
__device__ int   g_deg[NN_MAX];
__device__ int   g_rowptr[NN_MAX + 1];
__device__ int   g_cursor[NN_MAX];
__device__ int   g_bsum[512];
__device__ int   g_boff[512];
__device__ int2  g_eint[EE_MAX];    // {src, edge_attr bits}, sorted by dst

__device__ __forceinline__ void red_add_v2(float* p, float a, float b) {
    asm volatile("red.global.add.v2.f32 [%0], {%1,%2};"
                 :: "l"(p), "f"(a), "f"(b) : "memory");
}

// bf16 mma m16n8k16 (row.col)
__device__ __forceinline__ void mma_bf16(float d[4], const u32 a[4],
                                         const u32 b[2]) {
    asm("mma.sync.aligned.m16n8k16.row.col.f32.bf16.bf16.f32 "
        "{%0,%1,%2,%3}, {%4,%5,%6,%7}, {%8,%9}, {%0,%1,%2,%3};"
        : "+f"(d[0]), "+f"(d[1]), "+f"(d[2]), "+f"(d[3])
        : "r"(a[0]), "r"(a[1]), "r"(a[2]), "r"(a[3]), "r"(b[0]), "r"(b[1]));
}

__device__ __forceinline__ uint2 pack_bf16x4(float4 v) {
    __nv_bfloat162 p0 = __floats2bfloat162_rn(v.x, v.y);
    __nv_bfloat162 p1 = __floats2bfloat162_rn(v.z, v.w);
    uint2 o;
    o.x = *reinterpret_cast<u32*>(&p0);
    o.y = *reinterpret_cast<u32*>(&p1);
    return o;
}

__device__ __forceinline__ float4 ldhb4(const __nv_bfloat16* p) {
    uint2 rv = *(const uint2*)p;
    __nv_bfloat162 b0 = *reinterpret_cast<__nv_bfloat162*>(&rv.x);
    __nv_bfloat162 b1 = *reinterpret_cast<__nv_bfloat162*>(&rv.y);
    float2 f0 = __bfloat1622float2(b0);
    float2 f1 = __bfloat1622float2(b1);
    return make_float4(f0.x, f0.y, f1.x, f1.y);
}

// ---------------------------------------------------------------------------
// Fused init: dtype detect + zeroing + weight pre-convert, one kernel.
__global__ void init_kernel(const void* __restrict__ ei_raw,
                            const float* __restrict__ w1,
                            const float* __restrict__ w2, int n) {
    int i = blockIdx.x * blockDim.x + threadIdx.x;
    if (i == 0) {
        const long long* p = (const long long*)ei_raw;
        int ok = 1;
        for (int j = 0; j < 16; j++) {
            long long v = p[j];
            if (v < 0 || v >= (long long)n) ok = 0;
        }
        g_idx64 = ok;
    }
    if (i < n) g_deg[i] = 0;
    if (i < GG * HH) g_pool[i] = 0.0f;
    if (i < GG) g_cnt[i] = 0.0f;
    if (i < 2 * HH * HH) {
        int l = i >> 14;
        int off = i & 16383;
        int k = off >> 7;
        int c = off & 127;
        g_Wt[(l * 2 + 0) * 16384 + c * HH + k] = __float2bfloat16(__ldg(w1 + i));
        g_Wt[(l * 2 + 1) * 16384 + c * HH + k] = __float2bfloat16(__ldg(w2 + i));
    }
}

// ============================ CSR build (once) =============================
__global__ void csr_count_kernel(const void* __restrict__ ei_raw, int E, int n) {
    int e = blockIdx.x * blockDim.x + threadIdx.x;
    if (e >= E) return;
    long long dst;
    if (g_idx64) dst = __ldg((const long long*)ei_raw + E + e);
    else         dst = __ldg((const int*)ei_raw + E + e);
    if ((unsigned long long)dst >= (unsigned long long)n) return;
    atomicAdd(&g_deg[(int)dst], 1);
}

__global__ void blocksum_kernel(int n) {
    __shared__ int s[256];
    int t = threadIdx.x;
    int i = blockIdx.x * 256 + t;
    s[t] = (i < n) ? g_deg[i] : 0;
    __syncthreads();
    for (int d = 128; d > 0; d >>= 1) {
        if (t < d) s[t] += s[t + d];
        __syncthreads();
    }
    if (t == 0) g_bsum[blockIdx.x] = s[0];
}

__global__ void scan_bsum_kernel(int nb) {
    __shared__ int s[512];
    int t = threadIdx.x;
    int v0 = (t < nb) ? g_bsum[t] : 0;
    s[t] = v0;
    __syncthreads();
    for (int d = 1; d < 512; d <<= 1) {
        int v = (t >= d) ? s[t - d] : 0;
        __syncthreads();
        s[t] += v;
        __syncthreads();
    }
    g_boff[t] = s[t] - v0;
}

__global__ void rowptr_kernel(int n, int E) {
    __shared__ int s[256];
    int t = threadIdx.x;
    int i = blockIdx.x * 256 + t;
    int d = (i < n) ? g_deg[i] : 0;
    s[t] = d;
    __syncthreads();
    for (int dd = 1; dd < 256; dd <<= 1) {
        int v = (t >= dd) ? s[t - dd] : 0;
        __syncthreads();
        s[t] += v;
        __syncthreads();
    }
    int excl = s[t] - d + g_boff[blockIdx.x];
    if (i < n) {
        g_rowptr[i] = excl;
        g_cursor[i] = excl;
        if (i == n - 1) g_rowptr[n] = E;
    }
}

__global__ void csr_fill_kernel(const void* __restrict__ ei_raw,
                                const float* __restrict__ edge_attr,
                                int E, int n) {
    int e = blockIdx.x * blockDim.x + threadIdx.x;
    if (e >= E) return;
    long long src, dst;
    if (g_idx64) {
        const long long* ei = (const long long*)ei_raw;
        src = __ldg(ei + e);
        dst = __ldg(ei + E + e);
    } else {
        const int* ei = (const int*)ei_raw;
        src = __ldg(ei + e);
        dst = __ldg(ei + E + e);
    }
    if ((unsigned long long)src >= (unsigned long long)n ||
        (unsigned long long)dst >= (unsigned long long)n) return;
    int pos = atomicAdd(&g_cursor[(int)dst], 1);
    g_eint[pos] = make_int2((int)src, __float_as_int(__ldg(edge_attr + e)));
}

// ==================== aggregate layer 0 (rank-1 h) ==========================
__global__ void aggregate_l0_kernel(const float* __restrict__ x,
                                    const float* __restrict__ enc_w,
                                    const float* __restrict__ enc_b,
                                    const float* __restrict__ edge_w,
                                    const float* __restrict__ edge_b,
                                    const float* __restrict__ eps0, int n) {
    int gt = blockIdx.x * blockDim.x + threadIdx.x;
    int i = gt >> 5;
    if (i >= n) return;
    int lane = gt & 31;
    int c = lane * 4;
    float4 cw = *(const float4*)(enc_w + c);
    float4 cb = *(const float4*)(enc_b + c);
    float4 ew = *(const float4*)(edge_w + c);
    float4 eb = *(const float4*)(edge_b + c);
    float4 mb;
    mb.x = cb.x + eb.x; mb.y = cb.y + eb.y;
    mb.z = cb.z + eb.z; mb.w = cb.w + eb.w;
    float s = 1.0f + __ldg(eps0);
    float xi = __ldg(x + i);
    float4 acc;
    acc.x = s * fmaf(xi, cw.x, cb.x);
    acc.y = s * fmaf(xi, cw.y, cb.y);
    acc.z = s * fmaf(xi, cw.z, cb.z);
    acc.w = s * fmaf(xi, cw.w, cb.w);

    int k0 = __ldg(&g_rowptr[i]);
    int k1 = __ldg(&g_rowptr[i + 1]);
    for (int k = k0; k < k1; k++) {
        int2 ei = __ldg(&g_eint[k]);
        float xs = __ldg(x + ei.x);
        float ea = __int_as_float(ei.y);
        acc.x += fmaxf(fmaf(xs, cw.x, fmaf(ea, ew.x, mb.x)), 0.0f);
        acc.y += fmaxf(fmaf(xs, cw.y, fmaf(ea, ew.y, mb.y)), 0.0f);
        acc.z += fmaxf(fmaf(xs, cw.z, fmaf(ea, ew.z, mb.z)), 0.0f);
        acc.w += fmaxf(fmaf(xs, cw.w, fmaf(ea, ew.w, mb.w)), 0.0f);
    }
    *(uint2*)(g_aggrb + (size_t)i * HH + c) = pack_bf16x4(acc);
}

// ==================== aggregate layer 1 (bf16 h gather) =====================
__global__ void aggregate_kernel(const float* __restrict__ edge_w,
                                 const float* __restrict__ edge_b,
                                 const float* __restrict__ eps_l, int n) {
    int gt = blockIdx.x * blockDim.x + threadIdx.x;
    int i = gt >> 5;
    if (i >= n) return;
    int lane = gt & 31;
    int c = lane * 4;
    float4 ew = *(const float4*)(edge_w + c);
    float4 eb = *(const float4*)(edge_b + c);
    float s = 1.0f + __ldg(eps_l);

    float4 hv = ldhb4(g_hb + (size_t)i * HH + c);
    float4 acc;
    acc.x = hv.x * s; acc.y = hv.y * s; acc.z = hv.z * s; acc.w = hv.w * s;

    int k0 = __ldg(&g_rowptr[i]);
    int k1 = __ldg(&g_rowptr[i + 1]);
    int k = k0;
    for (; k + 8 <= k1; k += 8) {
        int2 ei[8]; float4 vv[8];
        #pragma unroll
        for (int u = 0; u < 8; u++) ei[u] = __ldg(&g_eint[k + u]);
        #pragma unroll
        for (int u = 0; u < 8; u++)
            vv[u] = ldhb4(g_hb + (size_t)ei[u].x * HH + c);
        #pragma unroll
        for (int u = 0; u < 8; u++) {
            float ea = __int_as_float(ei[u].y);
            acc.x += fmaxf(vv[u].x + fmaf(ea, ew.x, eb.x), 0.0f);
            acc.y += fmaxf(vv[u].y + fmaf(ea, ew.y, eb.y), 0.0f);
            acc.z += fmaxf(vv[u].z + fmaf(ea, ew.z, eb.z), 0.0f);
            acc.w += fmaxf(vv[u].w + fmaf(ea, ew.w, eb.w), 0.0f);
        }
    }
    for (; k < k1; k++) {
        int2 ei = __ldg(&g_eint[k]);
        float ea = __int_as_float(ei.y);
        float4 sv = ldhb4(g_hb + (size_t)ei.x * HH + c);
        acc.x += fmaxf(sv.x + fmaf(ea, ew.x, eb.x), 0.0f);
        acc.y += fmaxf(sv.y + fmaf(ea, ew.y, eb.y), 0.0f);
        acc.z += fmaxf(sv.z + fmaf(ea, ew.z, eb.z), 0.0f);
        acc.w += fmaxf(sv.w + fmaf(ea, ew.w, eb.w), 0.0f);
    }
    *(uint2*)(g_aggrb + (size_t)i * HH + c) = pack_bf16x4(acc);
}

// ---------------------------------------------------------------------------
// Fused MLP, resident-weights version: W1, W2, and the A/Z union all live in
// dynamic smem (stride 136 halves, conflict-free frag reads). All global->smem
// fills happen once up front; both MMA phases run with NO interior barriers.
// 3 syncthreads total (was 32).
// OUTK 1: bf16 -> g_hb.  OUTK 2: pool reduction.
#define SST 136                    // stride in halves (272 B)
#define TILE_H (128 * SST)         // halves per tile (34816 B)
template <int OUTK, int L>
__global__ void __launch_bounds__(256, 2)
mlp_fused_kernel(const float* __restrict__ b1,
                 const float* __restrict__ b2,
                 const float* __restrict__ bn_g,
                 const float* __restrict__ bn_b,
                 const float* __restrict__ bn_m,
                 const float* __restrict__ bn_v,
                 const void* __restrict__ batch_raw,
                 int M) {
    extern __shared__ __nv_bfloat16 smem[];
    __nv_bfloat16* sW1 = smem;                 // [c][k] stride SST
    __nv_bfloat16* sW2 = smem + TILE_H;
    __nv_bfloat16* sAZ = smem + 2 * TILE_H;    // phase1: A [r][k]; then Z [r][c]

    int tid = threadIdx.x;
    int lane = tid & 31;
    int wid = tid >> 5;
    int g = lane >> 2;
    int tig = lane & 3;
    int wr = wid >> 2;
    int wc = wid & 3;
    int row0 = blockIdx.x * 128;

    // ---- one-time fills: W1, W2, A (8 uint4 per tile per thread) ----
    int fr = tid >> 1;             // row/col 0..127
    int fho = (tid & 1) * 64;      // half-offset within row (0 or 64)
    {
        const __nv_bfloat16* W1 = g_Wt + (size_t)(2 * L + 0) * 16384;
        const __nv_bfloat16* W2 = g_Wt + (size_t)(2 * L + 1) * 16384;
        const uint4* w1p = (const uint4*)(W1 + fr * HH + fho);
        const uint4* w2p = (const uint4*)(W2 + fr * HH + fho);
        uint4* d1 = (uint4*)(sW1 + fr * SST + fho);
        uint4* d2 = (uint4*)(sW2 + fr * SST + fho);
        #pragma unroll
        for (int j = 0; j < 8; j++) {
            d1[j] = __ldg(w1p + j);
            d2[j] = __ldg(w2p + j);
        }
        int grow = row0 + fr;
        uint4* da = (uint4*)(sAZ + fr * SST + fho);
        if (grow < M) {
            const uint4* ap = (const uint4*)(g_aggrb + (size_t)grow * HH + fho);
            #pragma unroll
            for (int j = 0; j < 8; j++) da[j] = __ldg(ap + j);
        } else {
            #pragma unroll
            for (int j = 0; j < 8; j++) da[j] = make_uint4(0u, 0u, 0u, 0u);
        }
    }
    __syncthreads();

    float d[4][4][4];
    #pragma unroll
    for (int i = 0; i < 4; i++)
        #pragma unroll
        for (int j = 0; j < 4; j++)
            #pragma unroll
            for (int r = 0; r < 4; r++) d[i][j][r] = 0.0f;

    // ------------------ phase 1: A @ W1 (no barriers) ------------------
    #pragma unroll
    for (int k0 = 0; k0 < HH; k0 += 16) {
        u32 bf[4][2];
        #pragma unroll
        for (int nt = 0; nt < 4; nt++) {
            int cc = wc * 32 + nt * 8 + g;
            bf[nt][0] = *(const u32*)(sW1 + cc * SST + k0 + 2 * tig);
            bf[nt][1] = *(const u32*)(sW1 + cc * SST + k0 + 2 * tig + 8);
        }
        #pragma unroll
        for (int mt = 0; mt < 4; mt++) {
            int rr = wr * 64 + mt * 16 + g;
            u32 a[4];
            a[0] = *(const u32*)(sAZ + rr * SST + k0 + 2 * tig);
            a[1] = *(const u32*)(sAZ + (rr + 8) * SST + k0 + 2 * tig);
            a[2] = *(const u32*)(sAZ + rr * SST + k0 + 2 * tig + 8);
            a[3] = *(const u32*)(sAZ + (rr + 8) * SST + k0 + 2 * tig + 8);
            #pragma unroll
            for (int nt = 0; nt < 4; nt++)
                mma_bf16(d[mt][nt], a, bf[nt]);
        }
    }

    __syncthreads();   // all warps done reading A before Z overwrites it

    // epilogue 1: z = relu(d + b1) -> sAZ (as Z), reset d
    #pragma unroll
    for (int nt = 0; nt < 4; nt++) {
        int c = wc * 32 + nt * 8 + 2 * tig;
        float2 bb = *(const float2*)(b1 + c);
        #pragma unroll
        for (int mt = 0; mt < 4; mt++) {
            int r0 = wr * 64 + mt * 16 + g;
            float z0 = fmaxf(d[mt][nt][0] + bb.x, 0.0f);
            float z1 = fmaxf(d[mt][nt][1] + bb.y, 0.0f);
            float z2 = fmaxf(d[mt][nt][2] + bb.x, 0.0f);
            float z3 = fmaxf(d[mt][nt][3] + bb.y, 0.0f);
            *(__nv_bfloat162*)(sAZ + r0 * SST + c) = __floats2bfloat162_rn(z0, z1);
            *(__nv_bfloat162*)(sAZ + (r0 + 8) * SST + c) = __floats2bfloat162_rn(z2, z3);
            d[mt][nt][0] = 0.0f; d[mt][nt][1] = 0.0f;
            d[mt][nt][2] = 0.0f; d[mt][nt][3] = 0.0f;
        }
    }

    __syncthreads();   // Z complete

    // ------------------ phase 2: Z @ W2 (no barriers) ------------------
    #pragma unroll
    for (int k0 = 0; k0 < HH; k0 += 16) {
        u32 bf[4][2];
        #pragma unroll
        for (int nt = 0; nt < 4; nt++) {
            int cc = wc * 32 + nt * 8 + g;
            bf[nt][0] = *(const u32*)(sW2 + cc * SST + k0 + 2 * tig);
            bf[nt][1] = *(const u32*)(sW2 + cc * SST + k0 + 2 * tig + 8);
        }
        #pragma unroll
        for (int mt = 0; mt < 4; mt++) {
            int rr = wr * 64 + mt * 16 + g;
            u32 a[4];
            a[0] = *(const u32*)(sAZ + rr * SST + k0 + 2 * tig);
            a[1] = *(const u32*)(sAZ + (rr + 8) * SST + k0 + 2 * tig);
            a[2] = *(const u32*)(sAZ + rr * SST + k0 + 2 * tig + 8);
            a[3] = *(const u32*)(sAZ + (rr + 8) * SST + k0 + 2 * tig + 8);
            #pragma unroll
            for (int nt = 0; nt < 4; nt++)
                mma_bf16(d[mt][nt], a, bf[nt]);
        }
    }

    // epilogue 2: bias + BN + relu -> OUTK
    float2 bb[4], ssv[4], ttv[4];
    #pragma unroll
    for (int nt = 0; nt < 4; nt++) {
        int c = wc * 32 + nt * 8 + 2 * tig;
        bb[nt] = *(const float2*)(b2 + c);
        float2 bv = *(const float2*)(bn_v + c);
        float2 bg = *(const float2*)(bn_g + c);
        float2 bm = *(const float2*)(bn_m + c);
        float2 bbeta = *(const float2*)(bn_b + c);
        float i0 = rsqrtf(fabsf(bv.x) + 1e-5f);
        float i1 = rsqrtf(fabsf(bv.y) + 1e-5f);
        ssv[nt].x = bg.x * i0;
        ssv[nt].y = bg.y * i1;
        ttv[nt].x = bbeta.x - bm.x * ssv[nt].x;
        ttv[nt].y = bbeta.y - bm.y * ssv[nt].y;
    }

    #pragma unroll
    for (int mt = 0; mt < 4; mt++) {
        int r0 = row0 + wr * 64 + mt * 16 + g;
        int r1 = r0 + 8;
        long long b0 = 0, b1i = 0;
        if (OUTK == 2) {
            if (g_idx64) {
                if (r0 < M) b0  = __ldg((const long long*)batch_raw + r0);
                if (r1 < M) b1i = __ldg((const long long*)batch_raw + r1);
            } else {
                if (r0 < M) b0  = __ldg((const int*)batch_raw + r0);
                if (r1 < M) b1i = __ldg((const int*)batch_raw + r1);
            }
        }
        #pragma unroll
        for (int nt = 0; nt < 4; nt++) {
            int c = wc * 32 + nt * 8 + 2 * tig;
            float z0 = fmaf(d[mt][nt][0] + bb[nt].x, ssv[nt].x, ttv[nt].x);
            float z1 = fmaf(d[mt][nt][1] + bb[nt].y, ssv[nt].y, ttv[nt].y);
            float z2 = fmaf(d[mt][nt][2] + bb[nt].x, ssv[nt].x, ttv[nt].x);
            float z3 = fmaf(d[mt][nt][3] + bb[nt].y, ssv[nt].y, ttv[nt].y);
            z0 = fmaxf(z0, 0.0f); z1 = fmaxf(z1, 0.0f);
            z2 = fmaxf(z2, 0.0f); z3 = fmaxf(z3, 0.0f);
            if (OUTK == 2) {
                if (r0 < M && (unsigned long long)b0 < (unsigned long long)GG)
                    red_add_v2(g_pool + (size_t)b0 * HH + c, z0, z1);
                if (r1 < M && (unsigned long long)b1i < (unsigned long long)GG)
                    red_add_v2(g_pool + (size_t)b1i * HH + c, z2, z3);
            } else {
                if (r0 < M)
                    *(__nv_bfloat162*)(g_hb + (size_t)r0 * HH + c) =
                        __floats2bfloat162_rn(z0, z1);
                if (r1 < M)
                    *(__nv_bfloat162*)(g_hb + (size_t)r1 * HH + c) =
                        __floats2bfloat162_rn(z2, z3);
            }
        }
    }
}

// ---------------------------------------------------------------------------
__global__ void cnt_kernel(const void* __restrict__ batch_raw, int n) {
    int i = blockIdx.x * blockDim.x + threadIdx.x;
    if (i >= n) return;
    long long b;
    if (g_idx64) b = __ldg((const long long*)batch_raw + i);
    else         b = __ldg((const int*)batch_raw + i);
    if ((unsigned long long)b < (unsigned long long)GG)
        atomicAdd(&g_cnt[b], 1.0f);
}

// ---------------------------------------------------------------------------
// Per-graph classifier: one block per graph (64 blocks, 128 threads).
__global__ void classifier_kernel(const float* __restrict__ cls_w1,
                                  const float* __restrict__ cls_b1,
                                  const float* __restrict__ cls_w2,
                                  const float* __restrict__ cls_b2,
                                  float* __restrict__ out) {
    __shared__ float sg[HH];
    __shared__ float st[64];
    int gi = blockIdx.x;
    int tid = threadIdx.x;   // 128
    float cnt = fmaxf(g_cnt[gi], 1.0f);
    sg[tid] = g_pool[gi * HH + tid] / cnt;
    __syncthreads();
    if (tid < 64) {
        float s = cls_b1[tid];
        #pragma unroll 8
        for (int k = 0; k < HH; k++)
            s = fmaf(sg[k], cls_w1[k * 64 + tid], s);
        st[tid] = fmaxf(s, 0.0f);
    }
    __syncthreads();
    if (tid == 0) {
        float s = cls_b2[0];
        #pragma unroll 8
        for (int m = 0; m < 64; m++)
            s = fmaf(st[m], cls_w2[m], s);
        out[gi] = 1.0f / (1.0f + expf(-s));
    }
}

// ---------------------------------------------------------------------------
extern "C" void kernel_launch(void* const* d_in, const int* in_sizes, int n_in,
                              void* d_out, int out_size) {
    const float *x, *edge_attr, *enc_w, *enc_b, *edge_w, *edge_b, *eps;
    const float *mlp_w1, *mlp_b1, *mlp_w2, *mlp_b2;
    const float *bn_gamma, *bn_beta, *bn_mean, *bn_var;
    const float *cls_w1, *cls_b1, *cls_w2, *cls_b2;
    const void *edge_index, *batch;
    int n, E;

    if (in_sizes[1] > 1000) {
        x          = (const float*)d_in[0];
        edge_index = d_in[1];
        edge_attr  = (const float*)d_in[2];
        batch      = d_in[3];
        enc_w      = (const float*)d_in[4];
        enc_b      = (const float*)d_in[5];
        edge_w     = (const float*)d_in[6];
        edge_b     = (const float*)d_in[7];
        eps        = (const float*)d_in[8];
        mlp_w1     = (const float*)d_in[9];
        mlp_b1     = (const float*)d_in[10];
        mlp_w2     = (const float*)d_in[11];
        mlp_b2     = (const float*)d_in[12];
        bn_gamma   = (const float*)d_in[13];
        bn_beta    = (const float*)d_in[14];
        bn_mean    = (const float*)d_in[15];
        bn_var     = (const float*)d_in[16];
        cls_w1     = (const float*)d_in[17];
        cls_b1     = (const float*)d_in[18];
        cls_w2     = (const float*)d_in[19];
        cls_b2     = (const float*)d_in[20];
        n = in_sizes[0];
        E = in_sizes[2];
    } else {
        batch      = d_in[0];
        bn_beta    = (const float*)d_in[1];
        bn_gamma   = (const float*)d_in[2];
        bn_mean    = (const float*)d_in[3];
        bn_var     = (const float*)d_in[4];
        cls_b1     = (const float*)d_in[5];
        cls_b2     = (const float*)d_in[6];
        cls_w1     = (const float*)d_in[7];
        cls_w2     = (const float*)d_in[8];
        edge_attr  = (const float*)d_in[9];
        edge_b     = (const float*)d_in[10];
        edge_index = d_in[11];
        edge_w     = (const float*)d_in[12];
        enc_b      = (const float*)d_in[13];
        enc_w      = (const float*)d_in[14];
        eps        = (const float*)d_in[15];
        mlp_b1     = (const float*)d_in[16];
        mlp_b2     = (const float*)d_in[17];
        mlp_w1     = (const float*)d_in[18];
        mlp_w2     = (const float*)d_in[19];
        x          = (const float*)d_in[20];
        n = in_sizes[20];
        E = in_sizes[9];
    }
    float* out = (float*)d_out;
    if (E > EE_MAX) E = EE_MAX;

    const int mlp_smem = 3 * TILE_H * (int)sizeof(__nv_bfloat16);  // 104448 B
    cudaFuncSetAttribute(mlp_fused_kernel<1, 0>,
                         cudaFuncAttributeMaxDynamicSharedMemorySize, mlp_smem);
    cudaFuncSetAttribute(mlp_fused_kernel<2, 1>,
                         cudaFuncAttributeMaxDynamicSharedMemorySize, mlp_smem);

    int nblk = (n + 255) / 256;
    int gemm_blocks = (n + 127) / 128;
    int agg_blocks = (n * 32 + 255) / 256;

    // 0) fused init (detect + zero + weight pre-convert)
    init_kernel<<<nblk, 256>>>(edge_index, mlp_w1, mlp_w2, n);

    // 1) CSR build
    csr_count_kernel<<<(E + 255) / 256, 256>>>(edge_index, E, n);
    blocksum_kernel<<<nblk, 256>>>(n);
    scan_bsum_kernel<<<1, 512>>>(nblk);
    rowptr_kernel<<<nblk, 256>>>(n, E);
    csr_fill_kernel<<<(E + 255) / 256, 256>>>(edge_index, edge_attr, E, n);

    // 2) layers
    aggregate_l0_kernel<<<agg_blocks, 256>>>(x, enc_w, enc_b, edge_w, edge_b,
                                             eps, n);
    mlp_fused_kernel<1, 0><<<gemm_blocks, 256, mlp_smem>>>(
        mlp_b1, mlp_b2, bn_gamma, bn_beta, bn_mean, bn_var, nullptr, n);

    aggregate_kernel<<<agg_blocks, 256>>>(edge_w, edge_b, eps + 1, n);
    mlp_fused_kernel<2, 1><<<gemm_blocks, 256, mlp_smem>>>(
        mlp_b1 + HH, mlp_b2 + HH, bn_gamma + HH, bn_beta + HH,
        bn_mean + HH, bn_var + HH, batch, n);

    // 3) counts + classifier
    cnt_kernel<<<nblk, 256>>>(batch, n);
    classifier_kernel<<<GG, 128>>>(cls_w1, cls_b1, cls_w2, cls_b2, out);
}